// round 8
// baseline (speedup 1.0000x reference)
#include <cuda_runtime.h>
#include <cuda_bf16.h>

#define TPB     256
#define GRID_B  1024
#define MAX_B   1024
#define MAX_NT  2048
#define MAX_LL  8

// cross-kernel scratch (allocation-free). g_key/g_cnt zero at load and
// self-reset by the finisher -> deterministic across graph replays.
__device__ unsigned long long g_key[MAX_B];
__device__ int                g_cnt[MAX_B];
__device__ int                g_list[MAX_B];
__device__ int                g_nrej;

// ---------- Kernel A: token-parallel gather + per-request scan --------------
__global__ void __launch_bounds__(512)
scan_compact(const float* __restrict__ draft_probs,
             const float* __restrict__ target_probs,
             const float* __restrict__ uniform_probs,
             const int*   __restrict__ draft_token_ids,
             const int*   __restrict__ cu,
             const int*   __restrict__ bonus,
             float*       __restrict__ out,
             int B, int NT, int V, int L)
{
    __shared__ int   sid[MAX_NT];
    __shared__ float stp[MAX_NT];
    __shared__ float sdp[MAX_NT];
    __shared__ float su [MAX_NT];
    __shared__ int   scu[MAX_B];
    __shared__ int   wcnt[16];

    const int tid = threadIdx.x;

    // round 1: cu and token ids (independent)
    for (int r = tid; r < B; r += 512) scu[r] = __ldg(&cu[r]);
    for (int t = tid; t < NT; t += 512) sid[t] = __ldg(&draft_token_ids[t]);
    __syncthreads();          // need sid before prob gathers

    // round 2: prob/uniform gathers, token-parallel (one latency round)
    for (int t = tid; t < NT; t += 512) {
        const int idv = sid[t];
        stp[t] = __ldg(&target_probs[(size_t)t * V + idv]);
        sdp[t] = __ldg(&draft_probs [(size_t)t * V + idv]);
        su [t] = __ldg(&uniform_probs[t]);
    }
    __syncthreads();

    // per-request scan (threads 0..B-1), faithful to reference
    const int r     = tid;
    const bool activ = (r < B);
    int start = 0, end = 0;
    if (activ) { start = (r == 0) ? 0 : scu[r - 1]; end = scu[r]; }
    const int nd  = end - start;
    const int lim = (nd < L) ? nd : L;

    float pi = 1.0f, U = 1.0f;
    int last = -1;
    for (int j = 0; j < lim; j++) {
        const int t = start + j;
        const float dpj = sdp[t];
        const float ratio = (dpj > 0.0f) ? (stp[t] / dpj) : 1.0f;
        pi = fminf(pi * ratio, 1.0f);
        U *= su[t];
        if ((dpj > 0.0f) && (pi >= U)) last = j;
    }

    const int rejected  = (activ && nd > 0 && last != nd - 1) ? 1 : 0;
    const int write_col = rejected ? (last + 1) : nd;

    if (activ) {
        float* orow = out + (size_t)r * (L + 1);
        for (int j = 0; j <= L; j++) {
            float v = -1.0f;
            if (j < L && j <= last) v = (float)sid[start + j];
            orow[j] = v;
        }
        if (!rejected) orow[write_col] = (float)__ldg(&bonus[r]);
    }

    int rec = start + last + 1;
    rec = (rec < 0) ? 0 : rec;
    rec = (rec > NT - 1) ? (NT - 1) : rec;

    // compaction (ballot + cross-warp prefix; deterministic)
    const int warp = tid >> 5, lane = tid & 31;
    const unsigned ball = __ballot_sync(0xffffffffu, rejected);
    const int rank = __popc(ball & ((1u << lane) - 1));
    if (lane == 0) wcnt[warp] = __popc(ball);
    __syncthreads();
    int base = 0, total = 0;
    #pragma unroll
    for (int w = 0; w < 16; w++) {
        if (w < warp) base += wcnt[w];
        total += wcnt[w];
    }
    if (rejected)
        g_list[base + rank] = r | (write_col << 8) | (rec << 12);
    if (tid == 0) g_nrej = total;
}

// ---------- Kernel B: dynamic-split argmax over rejected rows ---------------
__global__ void __launch_bounds__(TPB)
argmax_kernel(const float* __restrict__ target_probs,
              float* __restrict__ out, int V, int L)
{
    const int nrej = g_nrej;
    if (nrej <= 0) return;

    // dynamic split: use the whole grid across the rejected rows
    const int nsplit = max(1, (int)gridDim.x / nrej);
    const int row    = blockIdx.x / nsplit;
    const int s      = blockIdx.x % nsplit;
    if (row >= nrej) return;

    const int chunk = (((V + nsplit - 1) / nsplit) + 3) & ~3;   // 4-aligned
    const int nact  = (V + chunk - 1) / chunk;                  // contributing splits
    if (s >= nact) return;
    const int beg = s * chunk;
    const int fin = min(V, beg + chunk);

    const int tid = threadIdx.x;
    const int e   = g_list[row];
    const int r   = e & 0xff;
    const int pos = (e >> 8) & 0xf;
    const int rec = e >> 12;

    const float*  rowp = target_probs + (size_t)rec * V;
    const float4* row4 = reinterpret_cast<const float4*>(rowp);
    const int n4beg = beg >> 2;
    const int n4end = fin >> 2;

    float  best  = -1.0f;      // probs >= 0
    int    bbase = -1;
    float4 bv    = make_float4(0.f, 0.f, 0.f, 0.f);

    for (int i0 = n4beg + tid; i0 < n4end; i0 += 8 * TPB) {
        float4 v[8];
        int    ix[8];
        #pragma unroll
        for (int k = 0; k < 8; k++) {
            ix[k] = i0 + k * TPB;
            const int safe = (ix[k] < n4end) ? ix[k] : i0;   // i0 always valid
            v[k] = __ldg(&row4[safe]);
        }
        #pragma unroll
        for (int k = 0; k < 8; k++) {
            const float m = fmaxf(fmaxf(v[k].x, v[k].y), fmaxf(v[k].z, v[k].w));
            if ((ix[k] < n4end) && (m > best)) {
                best = m; bbase = ix[k] << 2; bv = v[k];
            }
        }
    }

    int bidx = 0x7fffffff;
    if (bbase >= 0) {
        bidx = bbase + ((bv.x == best) ? 0 : (bv.y == best) ? 1
                      : (bv.z == best) ? 2 : 3);
    }
    // scalar tail (V not divisible by 4)
    {
        const int t0 = n4end << 2;
        if (tid < fin - t0) {
            const float vv = __ldg(&rowp[t0 + tid]);
            const int   ii = t0 + tid;
            if (vv > best || (vv == best && ii < bidx)) { best = vv; bidx = ii; }
        }
    }

    #pragma unroll
    for (int off = 16; off > 0; off >>= 1) {
        const float ov = __shfl_down_sync(0xffffffffu, best, off);
        const int   oi = __shfl_down_sync(0xffffffffu, bidx, off);
        if (ov > best || (ov == best && oi < bidx)) { best = ov; bidx = oi; }
    }

    __shared__ float wv[TPB / 32];
    __shared__ int   wi[TPB / 32];
    const int warp = tid >> 5, lane = tid & 31;
    if (lane == 0) { wv[warp] = best; wi[warp] = bidx; }
    __syncthreads();

    if (tid == 0) {
        #pragma unroll
        for (int ww = 1; ww < TPB / 32; ww++) {
            if (wv[ww] > best || (wv[ww] == best && wi[ww] < bidx)) {
                best = wv[ww]; bidx = wi[ww];
            }
        }
        // pack: prob bits (monotone for >=0 floats) | ~index (ties -> min idx)
        const unsigned long long key =
            ((unsigned long long)__float_as_uint(best) << 32) |
            (unsigned long long)(~(unsigned)bidx);
        atomicMax(&g_key[r], key);
        __threadfence();
        const int old = atomicAdd(&g_cnt[r], 1);
        if (old == nact - 1) {                       // last finisher
            const unsigned long long k = atomicMax(&g_key[r], 0ULL);
            const int idx = (int)(~(unsigned)(k & 0xffffffffULL));
            out[(size_t)r * (L + 1) + pos] = (float)idx;
            g_key[r] = 0ULL;                         // self-reset for replay
            g_cnt[r] = 0;
        }
    }
}

extern "C" void kernel_launch(void* const* d_in, const int* in_sizes, int n_in,
                              void* d_out, int out_size) {
    const float* draft_probs     = (const float*)d_in[0];
    const float* target_probs    = (const float*)d_in[1];
    const float* uniform_probs   = (const float*)d_in[2];
    const int*   draft_token_ids = (const int*)  d_in[3];
    const int*   cu              = (const int*)  d_in[4];
    const int*   bonus           = (const int*)  d_in[5];
    float*       out             = (float*)d_out;

    const int NT = in_sizes[3];
    const int B  = in_sizes[4];
    const int V  = in_sizes[0] / NT;
    const int L  = out_size / B - 1;

    scan_compact<<<1, 512>>>(draft_probs, target_probs, uniform_probs,
                             draft_token_ids, cu, bonus, out, B, NT, V, L);
    argmax_kernel<<<GRID_B, TPB>>>(target_probs, out, V, L);
}